// round 15
// baseline (speedup 1.0000x reference)
#include <cuda_runtime.h>
#include <math.h>
#include <stdint.h>

// Problem constants
#define BSZ 64
#define SEQ 512
#define DIM 768
#define NSPANS 1280
#define LMAX 5
#define H 200
#define G4 800          // 4*H
#define NENT 16
#define MROWS (NSPANS*LMAX)   // 6400

// Scratch (device globals)
__device__ float d_xg    [2ll * MROWS * G4];
__device__ float d_h     [2ll * 2 * NSPANS * H];   // [parity][dir][n][hh]
__device__ float d_c     [2ll * NSPANS * H];
__device__ float d_sum   [2ll * NSPANS * H];
__device__ int   d_offset[NSPANS + 1];
__device__ int   d_rowmap[MROWS];
__device__ unsigned d_barctr;

#define HBUF (2ll * NSPANS * H)
#define NBLK (13 * 20 * 2)     // recurrence grid size

// ---------------------------------------------------------------------------
// tf32 / mma helpers
// ---------------------------------------------------------------------------
__device__ __forceinline__ uint32_t f2tf32(float f) {
    uint32_t r;
    asm("cvt.rna.tf32.f32 %0, %1;" : "=r"(r) : "f"(f));
    return r;
}

__device__ __forceinline__ void mma_tf32(float* c, const uint32_t* a, const uint32_t* b) {
    asm volatile(
        "mma.sync.aligned.m16n8k8.row.col.f32.tf32.tf32.f32 "
        "{%0,%1,%2,%3}, {%4,%5,%6,%7}, {%8,%9}, {%0,%1,%2,%3};"
        : "+f"(c[0]), "+f"(c[1]), "+f"(c[2]), "+f"(c[3])
        : "r"(a[0]), "r"(a[1]), "r"(a[2]), "r"(a[3]), "r"(b[0]), "r"(b[1]));
}

__device__ __forceinline__ float sigm(float x) { return 1.f / (1.f + expf(-x)); }

#define BK 32
#define PAD 4
#define LDSROW (BK + PAD)      // 36 uints per row (proven layout)

// Device-wide barrier: every block arrives once; proceed when all arrived.
// All 520 blocks are co-resident (launch_bounds(256,5): 5 blocks/SM x 148 = 740).
__device__ __forceinline__ void global_barrier(unsigned target) {
    __syncthreads();
    if (threadIdx.x == 0) {
        __threadfence();
        atomicAdd(&d_barctr, 1u);
        volatile unsigned* p = &d_barctr;
        while (*p < target) { }
        __threadfence();
    }
    __syncthreads();
}

// ---------------------------------------------------------------------------
// Compaction: offsets = exclusive-prefix(slen); rowmap; reset barrier counter
// ---------------------------------------------------------------------------
__global__ void compact_kernel(const int* __restrict__ slen)
{
    __shared__ int part[256];
    int tid = threadIdx.x;
    if (tid == 0) d_barctr = 0u;
    int base = tid * 5;
    int loc[5], s = 0;
#pragma unroll
    for (int i = 0; i < 5; i++) { loc[i] = s; s += slen[base + i]; }
    part[tid] = s;
    __syncthreads();
    for (int off = 1; off < 256; off <<= 1) {
        int v = (tid >= off) ? part[tid - off] : 0;
        __syncthreads();
        part[tid] += v;
        __syncthreads();
    }
    int pre = (tid == 0) ? 0 : part[tid - 1];
#pragma unroll
    for (int i = 0; i < 5; i++) {
        int n = base + i;
        int off = pre + loc[i];
        d_offset[n] = off;
        int ln = slen[n];
        for (int l = 0; l < ln; l++)
            d_rowmap[off + l] = (n << 3) | l;
    }
    if (tid == 255) d_offset[NSPANS] = part[255];
}

// ---------------------------------------------------------------------------
// xg GEMM, fused gather, compacted rows (R8 proven: BM=128, BN=64)
// ---------------------------------------------------------------------------
__global__ __launch_bounds__(256)
void gemm_xg_kernel(const float* __restrict__ hidden,
                    const int* __restrict__ tok,
                    const int* __restrict__ slen,
                    const int* __restrict__ sbatch,
                    const float* __restrict__ Wf, const float* __restrict__ bif,
                    const float* __restrict__ bhf,
                    const float* __restrict__ Wb, const float* __restrict__ bib,
                    const float* __restrict__ bhb)
{
    const int BM = 128, BN = 64, K = DIM, N = G4;
    int m0 = blockIdx.y * BM;
    int count = d_offset[NSPANS];
    if (m0 >= count) return;

    __shared__ uint32_t As[BM][LDSROW];
    __shared__ uint32_t Bs[BN][LDSROW];
    __shared__ const float* rowptr[BM];

    int dir = blockIdx.z;
    const float* W  = dir ? Wb : Wf;
    const float* c1 = dir ? bib : bif;
    const float* c2 = dir ? bhb : bhf;
    float* C        = d_xg + (size_t)dir * MROWS * G4;

    int tid  = threadIdx.x;
    int warp = tid >> 5, lane = tid & 31;
    int wm = warp & 3, wn = warp >> 2;
    int grp = lane >> 2, qid = lane & 3;
    int n0 = blockIdx.x * BN;

    if (tid < BM) {
        int r = m0 + tid;
        const float* p = nullptr;
        if (r < count) {
            int rm = d_rowmap[r];
            int n  = rm >> 3;
            int l  = rm & 7;
            int ln = slen[n];
            int sl = dir ? (ln - 1 - l) : l;
            int t  = tok[n * LMAX + sl];
            int b  = sbatch[n];
            p = hidden + ((size_t)b * SEQ + t) * DIM;
        }
        rowptr[tid] = p;
    }
    __syncthreads();

    float acc[2][4][4];
#pragma unroll
    for (int i = 0; i < 2; i++)
#pragma unroll
        for (int j = 0; j < 4; j++)
#pragma unroll
            for (int q = 0; q < 4; q++) acc[i][j][q] = 0.f;

    const int lrow = tid >> 3;
    const int lcol = (tid & 7) * 4;

    for (int kt = 0; kt < K; kt += BK) {
#pragma unroll
        for (int p = 0; p < BM / 32; p++) {
            int m = lrow + p * 32;
            const float* src = rowptr[m];
            float4 v = make_float4(0.f, 0.f, 0.f, 0.f);
            if (src)
                v = *(const float4*)(src + kt + lcol);
            uint4 t;
            t.x = f2tf32(v.x); t.y = f2tf32(v.y);
            t.z = f2tf32(v.z); t.w = f2tf32(v.w);
            *(uint4*)&As[m][lcol] = t;
        }
#pragma unroll
        for (int p = 0; p < BN / 32; p++) {
            int n = lrow + p * 32;
            float4 v = make_float4(0.f, 0.f, 0.f, 0.f);
            if (n0 + n < N)
                v = *(const float4*)(W + (size_t)(n0 + n) * DIM + kt + lcol);
            uint4 t;
            t.x = f2tf32(v.x); t.y = f2tf32(v.y);
            t.z = f2tf32(v.z); t.w = f2tf32(v.w);
            *(uint4*)&Bs[n][lcol] = t;
        }
        __syncthreads();

#pragma unroll
        for (int ks = 0; ks < BK / 8; ks++) {
            uint32_t af[2][4], bf[4][2];
#pragma unroll
            for (int i = 0; i < 2; i++) {
                int mr = wm * 32 + i * 16;
                af[i][0] = As[mr + grp    ][ks * 8 + qid    ];
                af[i][1] = As[mr + grp + 8][ks * 8 + qid    ];
                af[i][2] = As[mr + grp    ][ks * 8 + qid + 4];
                af[i][3] = As[mr + grp + 8][ks * 8 + qid + 4];
            }
#pragma unroll
            for (int j = 0; j < 4; j++) {
                int nr = wn * 32 + j * 8;
                bf[j][0] = Bs[nr + grp][ks * 8 + qid    ];
                bf[j][1] = Bs[nr + grp][ks * 8 + qid + 4];
            }
#pragma unroll
            for (int i = 0; i < 2; i++)
#pragma unroll
                for (int j = 0; j < 4; j++)
                    mma_tf32(acc[i][j], af[i], bf[j]);
        }
        __syncthreads();
    }

#pragma unroll
    for (int i = 0; i < 2; i++) {
#pragma unroll
        for (int j = 0; j < 4; j++) {
            int m = m0 + wm * 32 + i * 16 + grp;
            int n = n0 + wn * 32 + j * 8 + qid * 2;
            if (n < N) {
                float bb0 = c1[n] + c2[n];
                float bb1 = c1[n + 1] + c2[n + 1];
                C[(size_t)m * G4 + n]           = acc[i][j][0] + bb0;
                C[(size_t)m * G4 + n + 1]       = acc[i][j][1] + bb1;
                C[(size_t)(m + 8) * G4 + n]     = acc[i][j][2] + bb0;
                C[(size_t)(m + 8) * G4 + n + 1] = acc[i][j][3] + bb1;
            }
        }
    }
}

// ---------------------------------------------------------------------------
// Single-launch recurrence: cell0 + 4 fused hh GEMM+cell steps + logits,
// separated by device-wide spin barriers. Grid (13, 20, 2) = 520 blocks,
// all co-resident via __launch_bounds__(256, 5).
// Per-step body = R8's proven BM=64/BN=64(4gx16hh)/BK=32 tile.
// smem: union of tiles (18432 B), Gs (17408 B), Es for logits (25600 B).
// ---------------------------------------------------------------------------
__global__ __launch_bounds__(256, 5)
void recurrence_kernel(const float* __restrict__ Wf, const float* __restrict__ Wb,
                       const int* __restrict__ slen,
                       const float* __restrict__ E, float* __restrict__ out)
{
    const int BM = 64, BN = 64, K = H;

    __shared__ __align__(16) unsigned char smbuf[25600];
    uint32_t* As = (uint32_t*)smbuf;                 // [BM][36]
    uint32_t* Bs = As + BM * LDSROW;                 // [BN][36]
    float*    Gs = (float*)smbuf;                    // [BM][68] alias
    float*    Es = (float*)smbuf;                    // logits E stage alias
    __shared__ int offs[BM];
    __shared__ int lens[BM];

    int dir = blockIdx.z;
    const float* W  = dir ? Wb : Wf;
    const float* XG = d_xg + (size_t)dir * MROWS * G4;

    int tid  = threadIdx.x;
    int warp = tid >> 5, lane = tid & 31;
    int wm = warp & 1, wn = warp >> 1;
    int grp = lane >> 2, qid = lane & 3;
    int m0 = blockIdx.y * BM;
    int hh_base = blockIdx.x * 16;

    if (tid < BM) {
        int n = m0 + tid;
        lens[tid] = slen[n];
        offs[tid] = d_offset[n];
    }
    __syncthreads();

    // ---- t = 0 cell for this block's 64 spans x 16 hh slice (h=0) ----
#pragma unroll
    for (int it = 0; it < 4; it++) {
        int id = tid + it * 256;
        int m  = id >> 4;
        int hl = id & 15;
        int hhi = hh_base + hl;
        if (hhi >= H) continue;
        const float* g = XG + (size_t)offs[m] * G4 + hhi;
        float gi = g[0];
        float gg = g[2 * H];
        float go = g[3 * H];
        float cn = sigm(gi) * tanhf(gg);
        float hn = sigm(go) * tanhf(cn);
        size_t sidx = (size_t)dir * NSPANS * H + (size_t)(m0 + m) * H + hhi;
        d_c[sidx] = cn;
        d_h[sidx] = hn;                 // parity 0
        d_sum[sidx] = hn;               // slen >= 1
    }
    global_barrier(NBLK);

    // ---- steps t = 1..4 ----
    const int lrow = tid >> 3;
    const int lcol = (tid & 7) * 4;

    for (int t = 1; t < LMAX; t++) {
        const float* A     = d_h + ((t - 1) & 1) * HBUF + (size_t)dir * NSPANS * H;
        float*       h_out = d_h + (t & 1) * HBUF;

        float acc[2][2][4];
#pragma unroll
        for (int i = 0; i < 2; i++)
#pragma unroll
            for (int j = 0; j < 2; j++)
#pragma unroll
                for (int q = 0; q < 4; q++) acc[i][j][q] = 0.f;

        for (int kt = 0; kt < K; kt += BK) {
            // A tile
#pragma unroll
            for (int p = 0; p < BM / 32; p++) {
                int m = lrow + p * 32;
                int k = kt + lcol;
                float4 v = make_float4(0.f, 0.f, 0.f, 0.f);
                if (k < K)
                    v = *(const float4*)(A + (size_t)(m0 + m) * H + k);
                uint4 tt;
                tt.x = f2tf32(v.x); tt.y = f2tf32(v.y);
                tt.z = f2tf32(v.z); tt.w = f2tf32(v.w);
                *(uint4*)&As[m * LDSROW + lcol] = tt;
            }
            // B tile: row map n -> (n>>4)*H + hh_base + (n&15)
#pragma unroll
            for (int p = 0; p < BN / 32; p++) {
                int n = lrow + p * 32;
                int hhi = hh_base + (n & 15);
                int grow = (n >> 4) * H + hhi;
                int k = kt + lcol;
                float4 v = make_float4(0.f, 0.f, 0.f, 0.f);
                if (hhi < H && k < K)
                    v = *(const float4*)(W + (size_t)grow * H + k);
                uint4 tt;
                tt.x = f2tf32(v.x); tt.y = f2tf32(v.y);
                tt.z = f2tf32(v.z); tt.w = f2tf32(v.w);
                *(uint4*)&Bs[n * LDSROW + lcol] = tt;
            }
            __syncthreads();

#pragma unroll
            for (int ks = 0; ks < BK / 8; ks++) {
                uint32_t af[2][4], bf[2][2];
#pragma unroll
                for (int i = 0; i < 2; i++) {
                    int mr = wm * 32 + i * 16;
                    af[i][0] = As[(mr + grp    ) * LDSROW + ks * 8 + qid    ];
                    af[i][1] = As[(mr + grp + 8) * LDSROW + ks * 8 + qid    ];
                    af[i][2] = As[(mr + grp    ) * LDSROW + ks * 8 + qid + 4];
                    af[i][3] = As[(mr + grp + 8) * LDSROW + ks * 8 + qid + 4];
                }
#pragma unroll
                for (int j = 0; j < 2; j++) {
                    int nr = wn * 16 + j * 8;
                    bf[j][0] = Bs[(nr + grp) * LDSROW + ks * 8 + qid    ];
                    bf[j][1] = Bs[(nr + grp) * LDSROW + ks * 8 + qid + 4];
                }
#pragma unroll
                for (int i = 0; i < 2; i++)
#pragma unroll
                    for (int j = 0; j < 2; j++)
                        mma_tf32(acc[i][j], af[i], bf[j]);
            }
            __syncthreads();
        }

        // Stage gate tile into aliased Gs
#pragma unroll
        for (int i = 0; i < 2; i++) {
#pragma unroll
            for (int j = 0; j < 2; j++) {
                int m = wm * 32 + i * 16 + grp;
                int n = wn * 16 + j * 8 + qid * 2;
                Gs[m * 68 + n]           = acc[i][j][0];
                Gs[m * 68 + n + 1]       = acc[i][j][1];
                Gs[(m + 8) * 68 + n]     = acc[i][j][2];
                Gs[(m + 8) * 68 + n + 1] = acc[i][j][3];
            }
        }
        __syncthreads();

        // Cell phase: 64 spans x 16 hh, 4 items per thread
#pragma unroll
        for (int it = 0; it < 4; it++) {
            int id = tid + it * 256;
            int m  = id >> 4;
            int hl = id & 15;
            int hhi = hh_base + hl;
            if (hhi >= H) continue;

            int len = lens[m];
            int tt  = t < len ? t : (len - 1);
            size_t xb = (size_t)(offs[m] + tt) * G4 + hhi;
            float gi = Gs[m * 68 + hl     ] + XG[xb];
            float gf = Gs[m * 68 + 16 + hl] + XG[xb + H];
            float gg = Gs[m * 68 + 32 + hl] + XG[xb + 2 * H];
            float go = Gs[m * 68 + 48 + hl] + XG[xb + 3 * H];

            size_t sidx = (size_t)dir * NSPANS * H + (size_t)(m0 + m) * H + hhi;
            float cn = sigm(gf) * d_c[sidx] + sigm(gi) * tanhf(gg);
            float hn = sigm(go) * tanhf(cn);
            d_c[sidx]   = cn;
            h_out[sidx] = hn;
            if (t < len) d_sum[sidx] += hn;
        }
        global_barrier((unsigned)NBLK * (t + 1));
    }

    // ---- logits: 20 blocks (x==0, dir==0), 64 spans each ----
    if (blockIdx.x == 0 && dir == 0) {
        for (int i = tid; i < NENT * 2 * H; i += 256)
            Es[i] = E[i];
        __syncthreads();

#pragma unroll
        for (int it = 0; it < 4; it++) {
            int id = tid + it * 256;
            int sl = id >> 4;        // 0..63
            int e  = id & 15;
            int n  = m0 + sl;

            const float4* sf = (const float4*)(d_sum + (size_t)n * H);
            const float4* sb = (const float4*)(d_sum + (size_t)NSPANS * H + (size_t)n * H);
            const float4* er = (const float4*)(Es + e * 2 * H);

            float acc = 0.f;
#pragma unroll
            for (int j = 0; j < H / 4; j++) {
                float4 a = sf[j], b = er[j];
                acc += a.x * b.x + a.y * b.y + a.z * b.z + a.w * b.w;
            }
#pragma unroll
            for (int j = 0; j < H / 4; j++) {
                float4 a = sb[j], b = er[H / 4 + j];
                acc += a.x * b.x + a.y * b.y + a.z * b.z + a.w * b.w;
            }
            out[n * NENT + e] = acc;
        }
    }
}

// ---------------------------------------------------------------------------
// Launch
// ---------------------------------------------------------------------------
extern "C" void kernel_launch(void* const* d_in, const int* in_sizes, int n_in,
                              void* d_out, int out_size)
{
    const float* hidden = (const float*)d_in[0];
    const int*   tok    = (const int*)d_in[1];
    const int*   slen   = (const int*)d_in[2];
    const int*   sbatch = (const int*)d_in[3];
    const float* W_ih_f = (const float*)d_in[4];
    const float* W_hh_f = (const float*)d_in[5];
    const float* b_ih_f = (const float*)d_in[6];
    const float* b_hh_f = (const float*)d_in[7];
    const float* W_ih_b = (const float*)d_in[8];
    const float* W_hh_b = (const float*)d_in[9];
    const float* b_ih_b = (const float*)d_in[10];
    const float* b_hh_b = (const float*)d_in[11];
    const float* E      = (const float*)d_in[12];
    float* out          = (float*)d_out;

    // 0. Compaction + barrier-counter reset
    compact_kernel<<<1, 256>>>(slen);

    // 1. xg GEMM, fused gather, compacted rows: grid 13 x 50 x 2 (self-trim)
    {
        dim3 grid((G4 + 63) / 64, MROWS / 128, 2);
        gemm_xg_kernel<<<grid, 256>>>(hidden, tok, slen, sbatch,
                                      W_ih_f, b_ih_f, b_hh_f,
                                      W_ih_b, b_ih_b, b_hh_b);
    }

    // 2. Single-launch recurrence (cell0 + 4 steps + logits)
    {
        dim3 grid(13, 20, 2);
        recurrence_kernel<<<grid, 256>>>(W_hh_f, W_hh_b, slen, E, out);
    }
}

// round 16
// speedup vs baseline: 1.2705x; 1.2705x over previous
#include <cuda_runtime.h>
#include <math.h>
#include <stdint.h>

// Problem constants
#define BSZ 64
#define SEQ 512
#define DIM 768
#define NSPANS 1280
#define LMAX 5
#define H 200
#define G4 800          // 4*H
#define NENT 16
#define MROWS (NSPANS*LMAX)   // 6400

// Scratch (device globals)
__device__ float d_xg    [2ll * MROWS * G4];
__device__ float d_h     [2ll * 2 * NSPANS * H];   // [parity][dir][n][hh]
__device__ float d_c     [2ll * NSPANS * H];
__device__ float d_sum   [2ll * NSPANS * H];
__device__ int   d_offset[NSPANS + 1];
__device__ int   d_rowmap[MROWS];

#define HBUF (2ll * NSPANS * H)

// ---------------------------------------------------------------------------
// tf32 helpers
// ---------------------------------------------------------------------------
__device__ __forceinline__ uint32_t f2tf32(float f) {
    uint32_t r;
    asm("cvt.rna.tf32.f32 %0, %1;" : "=r"(r) : "f"(f));
    return r;
}

__device__ __forceinline__ void mma_tf32(float* c, const uint32_t* a, const uint32_t* b) {
    asm volatile(
        "mma.sync.aligned.m16n8k8.row.col.f32.tf32.tf32.f32 "
        "{%0,%1,%2,%3}, {%4,%5,%6,%7}, {%8,%9}, {%0,%1,%2,%3};"
        : "+f"(c[0]), "+f"(c[1]), "+f"(c[2]), "+f"(c[3])
        : "r"(a[0]), "r"(a[1]), "r"(a[2]), "r"(a[3]), "r"(b[0]), "r"(b[1]));
}

__device__ __forceinline__ float sigm(float x) { return 1.f / (1.f + expf(-x)); }

#define BK 32
#define PAD 4
#define LDSROW (BK + PAD)   // 36 uints per row (R4/R8 proven layout)

// ---------------------------------------------------------------------------
// Compaction: offsets = exclusive-prefix(slen); rowmap[off+l] = (n<<3)|l
// ---------------------------------------------------------------------------
__global__ void compact_kernel(const int* __restrict__ slen)
{
    __shared__ int part[256];
    int tid = threadIdx.x;
    int base = tid * 5;
    int loc[5], s = 0;
#pragma unroll
    for (int i = 0; i < 5; i++) { loc[i] = s; s += slen[base + i]; }
    part[tid] = s;
    __syncthreads();
    for (int off = 1; off < 256; off <<= 1) {
        int v = (tid >= off) ? part[tid - off] : 0;
        __syncthreads();
        part[tid] += v;
        __syncthreads();
    }
    int pre = (tid == 0) ? 0 : part[tid - 1];
#pragma unroll
    for (int i = 0; i < 5; i++) {
        int n = base + i;
        int off = pre + loc[i];
        d_offset[n] = off;
        int ln = slen[n];
        for (int l = 0; l < ln; l++)
            d_rowmap[off + l] = (n << 3) | l;
    }
    if (tid == 255) d_offset[NSPANS] = part[255];
}

// ---------------------------------------------------------------------------
// xg GEMM, fused gather, compacted rows (R8 proven: BM=128, BN=64)
// ---------------------------------------------------------------------------
__global__ __launch_bounds__(256)
void gemm_xg_kernel(const float* __restrict__ hidden,
                    const int* __restrict__ tok,
                    const int* __restrict__ slen,
                    const int* __restrict__ sbatch,
                    const float* __restrict__ Wf, const float* __restrict__ bif,
                    const float* __restrict__ bhf,
                    const float* __restrict__ Wb, const float* __restrict__ bib,
                    const float* __restrict__ bhb)
{
    const int BM = 128, BN = 64, K = DIM, N = G4;
    int m0 = blockIdx.y * BM;
    int count = d_offset[NSPANS];
    if (m0 >= count) return;

    __shared__ uint32_t As[BM][LDSROW];
    __shared__ uint32_t Bs[BN][LDSROW];
    __shared__ const float* rowptr[BM];

    int dir = blockIdx.z;
    const float* W  = dir ? Wb : Wf;
    const float* c1 = dir ? bib : bif;
    const float* c2 = dir ? bhb : bhf;
    float* C        = d_xg + (size_t)dir * MROWS * G4;

    int tid  = threadIdx.x;
    int warp = tid >> 5, lane = tid & 31;
    int wm = warp & 3, wn = warp >> 2;
    int grp = lane >> 2, qid = lane & 3;
    int n0 = blockIdx.x * BN;

    if (tid < BM) {
        int r = m0 + tid;
        const float* p = nullptr;
        if (r < count) {
            int rm = d_rowmap[r];
            int n  = rm >> 3;
            int l  = rm & 7;
            int ln = slen[n];
            int sl = dir ? (ln - 1 - l) : l;
            int t  = tok[n * LMAX + sl];
            int b  = sbatch[n];
            p = hidden + ((size_t)b * SEQ + t) * DIM;
        }
        rowptr[tid] = p;
    }
    __syncthreads();

    float acc[2][4][4];
#pragma unroll
    for (int i = 0; i < 2; i++)
#pragma unroll
        for (int j = 0; j < 4; j++)
#pragma unroll
            for (int q = 0; q < 4; q++) acc[i][j][q] = 0.f;

    const int lrow = tid >> 3;
    const int lcol = (tid & 7) * 4;

    for (int kt = 0; kt < K; kt += BK) {
#pragma unroll
        for (int p = 0; p < BM / 32; p++) {
            int m = lrow + p * 32;
            const float* src = rowptr[m];
            float4 v = make_float4(0.f, 0.f, 0.f, 0.f);
            if (src)
                v = *(const float4*)(src + kt + lcol);
            uint4 t;
            t.x = f2tf32(v.x); t.y = f2tf32(v.y);
            t.z = f2tf32(v.z); t.w = f2tf32(v.w);
            *(uint4*)&As[m][lcol] = t;
        }
#pragma unroll
        for (int p = 0; p < BN / 32; p++) {
            int n = lrow + p * 32;
            float4 v = make_float4(0.f, 0.f, 0.f, 0.f);
            if (n0 + n < N)
                v = *(const float4*)(W + (size_t)(n0 + n) * DIM + kt + lcol);
            uint4 t;
            t.x = f2tf32(v.x); t.y = f2tf32(v.y);
            t.z = f2tf32(v.z); t.w = f2tf32(v.w);
            *(uint4*)&Bs[n][lcol] = t;
        }
        __syncthreads();

#pragma unroll
        for (int ks = 0; ks < BK / 8; ks++) {
            uint32_t af[2][4], bf[4][2];
#pragma unroll
            for (int i = 0; i < 2; i++) {
                int mr = wm * 32 + i * 16;
                af[i][0] = As[mr + grp    ][ks * 8 + qid    ];
                af[i][1] = As[mr + grp + 8][ks * 8 + qid    ];
                af[i][2] = As[mr + grp    ][ks * 8 + qid + 4];
                af[i][3] = As[mr + grp + 8][ks * 8 + qid + 4];
            }
#pragma unroll
            for (int j = 0; j < 4; j++) {
                int nr = wn * 32 + j * 8;
                bf[j][0] = Bs[nr + grp][ks * 8 + qid    ];
                bf[j][1] = Bs[nr + grp][ks * 8 + qid + 4];
            }
#pragma unroll
            for (int i = 0; i < 2; i++)
#pragma unroll
                for (int j = 0; j < 4; j++)
                    mma_tf32(acc[i][j], af[i], bf[j]);
        }
        __syncthreads();
    }

#pragma unroll
    for (int i = 0; i < 2; i++) {
#pragma unroll
        for (int j = 0; j < 4; j++) {
            int m = m0 + wm * 32 + i * 16 + grp;
            int n = n0 + wn * 32 + j * 8 + qid * 2;
            if (n < N) {
                float bb0 = c1[n] + c2[n];
                float bb1 = c1[n + 1] + c2[n + 1];
                C[(size_t)m * G4 + n]           = acc[i][j][0] + bb0;
                C[(size_t)m * G4 + n + 1]       = acc[i][j][1] + bb1;
                C[(size_t)(m + 8) * G4 + n]     = acc[i][j][2] + bb0;
                C[(size_t)(m + 8) * G4 + n + 1] = acc[i][j][3] + bb1;
            }
        }
    }
}

// ---------------------------------------------------------------------------
// Fused hh GEMM + cell (R8 verbatim). BM=64 spans, BN=64 = 4 gates x 16 hh.
// Column map: local n -> W row (n>>4)*H + hh_base + (n&15).
// h double-buffered: reads parity (t-1)&1, writes t&1.
// grid = (13, 20, 2)
// ---------------------------------------------------------------------------
__global__ __launch_bounds__(256)
void gemm_hh_cell_kernel(const float* __restrict__ Wf, const float* __restrict__ Wb,
                         const int* __restrict__ slen, int t)
{
    const int BM = 64, BN = 64, K = H;
    __shared__ uint32_t As[BM][LDSROW];
    __shared__ uint32_t Bs[BN][LDSROW];
    __shared__ float Gs[BM][BN + 4];
    __shared__ int   xrow[BM];
    __shared__ int   lens[BM];

    int dir = blockIdx.z;
    const float* A     = d_h + ((t - 1) & 1) * HBUF + (size_t)dir * NSPANS * H;
    float*       h_out = d_h + (t & 1) * HBUF;
    const float* W  = dir ? Wb : Wf;
    const float* XG = d_xg + (size_t)dir * MROWS * G4;

    int tid  = threadIdx.x;
    int warp = tid >> 5, lane = tid & 31;
    int wm = warp & 1, wn = warp >> 1;
    int grp = lane >> 2, qid = lane & 3;
    int m0 = blockIdx.y * BM;
    int hh_base = blockIdx.x * 16;

    if (tid < BM) {
        int n  = m0 + tid;
        int ln = slen[n];
        lens[tid] = ln;
        int tt = t < ln ? t : (ln - 1);
        xrow[tid] = d_offset[n] + tt;
    }

    float acc[2][2][4];
#pragma unroll
    for (int i = 0; i < 2; i++)
#pragma unroll
        for (int j = 0; j < 2; j++)
#pragma unroll
            for (int q = 0; q < 4; q++) acc[i][j][q] = 0.f;

    const int lrow = tid >> 3;
    const int lcol = (tid & 7) * 4;

    for (int kt = 0; kt < K; kt += BK) {
#pragma unroll
        for (int p = 0; p < BM / 32; p++) {
            int m = lrow + p * 32;
            int k = kt + lcol;
            float4 v = make_float4(0.f, 0.f, 0.f, 0.f);
            if (k < K)
                v = *(const float4*)(A + (size_t)(m0 + m) * H + k);
            uint4 tt;
            tt.x = f2tf32(v.x); tt.y = f2tf32(v.y);
            tt.z = f2tf32(v.z); tt.w = f2tf32(v.w);
            *(uint4*)&As[m][lcol] = tt;
        }
#pragma unroll
        for (int p = 0; p < BN / 32; p++) {
            int n = lrow + p * 32;
            int hhi = hh_base + (n & 15);
            int grow = (n >> 4) * H + hhi;
            int k = kt + lcol;
            float4 v = make_float4(0.f, 0.f, 0.f, 0.f);
            if (hhi < H && k < K)
                v = *(const float4*)(W + (size_t)grow * H + k);
            uint4 tt;
            tt.x = f2tf32(v.x); tt.y = f2tf32(v.y);
            tt.z = f2tf32(v.z); tt.w = f2tf32(v.w);
            *(uint4*)&Bs[n][lcol] = tt;
        }
        __syncthreads();

#pragma unroll
        for (int ks = 0; ks < BK / 8; ks++) {
            uint32_t af[2][4], bf[2][2];
#pragma unroll
            for (int i = 0; i < 2; i++) {
                int mr = wm * 32 + i * 16;
                af[i][0] = As[mr + grp    ][ks * 8 + qid    ];
                af[i][1] = As[mr + grp + 8][ks * 8 + qid    ];
                af[i][2] = As[mr + grp    ][ks * 8 + qid + 4];
                af[i][3] = As[mr + grp + 8][ks * 8 + qid + 4];
            }
#pragma unroll
            for (int j = 0; j < 2; j++) {
                int nr = wn * 16 + j * 8;
                bf[j][0] = Bs[nr + grp][ks * 8 + qid    ];
                bf[j][1] = Bs[nr + grp][ks * 8 + qid + 4];
            }
#pragma unroll
            for (int i = 0; i < 2; i++)
#pragma unroll
                for (int j = 0; j < 2; j++)
                    mma_tf32(acc[i][j], af[i], bf[j]);
        }
        __syncthreads();
    }

    // Stage gate tile to smem
#pragma unroll
    for (int i = 0; i < 2; i++) {
#pragma unroll
        for (int j = 0; j < 2; j++) {
            int m = wm * 32 + i * 16 + grp;
            int n = wn * 16 + j * 8 + qid * 2;
            Gs[m][n]         = acc[i][j][0];
            Gs[m][n + 1]     = acc[i][j][1];
            Gs[m + 8][n]     = acc[i][j][2];
            Gs[m + 8][n + 1] = acc[i][j][3];
        }
    }
    __syncthreads();

    // Cell phase: 64x16 items, 4 per thread
#pragma unroll
    for (int it = 0; it < 4; it++) {
        int id = tid + it * 256;
        int m  = id >> 4;
        int hl = id & 15;
        int hhi = hh_base + hl;
        if (hhi >= H) continue;

        size_t xb = (size_t)xrow[m] * G4 + hhi;
        float gi = Gs[m][hl     ] + XG[xb];
        float gf = Gs[m][16 + hl] + XG[xb + H];
        float gg = Gs[m][32 + hl] + XG[xb + 2 * H];
        float go = Gs[m][48 + hl] + XG[xb + 3 * H];

        size_t sidx = (size_t)dir * NSPANS * H + (size_t)(m0 + m) * H + hhi;
        float cn = sigm(gf) * d_c[sidx] + sigm(gi) * tanhf(gg);
        float hn = sigm(go) * tanhf(cn);
        d_c[sidx]   = cn;
        h_out[sidx] = hn;
        if (t < lens[m]) d_sum[sidx] += hn;
    }
}

// ---------------------------------------------------------------------------
// t=0 cell: gates = xg[offset[n]] (h=0). Writes h parity 0, c, sum.
// ---------------------------------------------------------------------------
__global__ void lstm_cell0(const int* __restrict__ slen)
{
    int idx = blockIdx.x * blockDim.x + threadIdx.x;
    if (idx >= 2 * NSPANS * H) return;
    int hh  = idx % H;
    int n   = (idx / H) % NSPANS;
    int dir = idx / (H * NSPANS);

    int row = d_offset[n];
    const float* g = d_xg + (size_t)dir * MROWS * G4 + (size_t)row * G4;
    float gi = g[hh];
    float gg = g[2 * H + hh];
    float go = g[3 * H + hh];

    float cn = sigm(gi) * tanhf(gg);
    float hn = sigm(go) * tanhf(cn);
    d_c[idx] = cn;
    d_h[idx] = hn;                  // parity 0
    d_sum[idx] = hn;                // slen >= 1
}

// ---------------------------------------------------------------------------
// Logits with smem-staged E. 512 threads = 32 spans x 16 ents. grid = 40.
// ---------------------------------------------------------------------------
__global__ __launch_bounds__(512)
void logits_kernel(const float* __restrict__ E, float* __restrict__ out)
{
    __shared__ float Es[NENT * 2 * H];   // 25.6 KB
    int tid = threadIdx.x;
    for (int i = tid; i < NENT * 2 * H; i += 512)
        Es[i] = E[i];
    __syncthreads();

    int s = tid >> 4;
    int e = tid & 15;
    int n = blockIdx.x * 32 + s;

    const float4* sf = (const float4*)(d_sum + (size_t)n * H);
    const float4* sb = (const float4*)(d_sum + (size_t)NSPANS * H + (size_t)n * H);
    const float4* er = (const float4*)(Es + e * 2 * H);

    float acc = 0.f;
#pragma unroll
    for (int j = 0; j < H / 4; j++) {
        float4 a = sf[j], b = er[j];
        acc += a.x * b.x + a.y * b.y + a.z * b.z + a.w * b.w;
    }
#pragma unroll
    for (int j = 0; j < H / 4; j++) {
        float4 a = sb[j], b = er[H / 4 + j];
        acc += a.x * b.x + a.y * b.y + a.z * b.z + a.w * b.w;
    }
    out[n * NENT + e] = acc;
}

// ---------------------------------------------------------------------------
// Launch
// ---------------------------------------------------------------------------
extern "C" void kernel_launch(void* const* d_in, const int* in_sizes, int n_in,
                              void* d_out, int out_size)
{
    const float* hidden = (const float*)d_in[0];
    const int*   tok    = (const int*)d_in[1];
    const int*   slen   = (const int*)d_in[2];
    const int*   sbatch = (const int*)d_in[3];
    const float* W_ih_f = (const float*)d_in[4];
    const float* W_hh_f = (const float*)d_in[5];
    const float* b_ih_f = (const float*)d_in[6];
    const float* b_hh_f = (const float*)d_in[7];
    const float* W_ih_b = (const float*)d_in[8];
    const float* W_hh_b = (const float*)d_in[9];
    const float* b_ih_b = (const float*)d_in[10];
    const float* b_hh_b = (const float*)d_in[11];
    const float* E      = (const float*)d_in[12];
    float* out          = (float*)d_out;

    // 0. Row compaction
    compact_kernel<<<1, 256>>>(slen);

    // 1. xg GEMM, fused gather, compacted rows: grid 13 x 50 x 2 (self-trim)
    {
        dim3 grid((G4 + 63) / 64, MROWS / 128, 2);
        gemm_xg_kernel<<<grid, 256>>>(hidden, tok, slen, sbatch,
                                      W_ih_f, b_ih_f, b_hh_f,
                                      W_ih_b, b_ih_b, b_hh_b);
    }

    // 2. Recurrence
    {
        const int ct = 256;
        lstm_cell0<<<(2 * NSPANS * H + ct - 1) / ct, ct>>>(slen);
    }
    for (int t = 1; t < LMAX; t++) {
        dim3 grid((H + 15) / 16, NSPANS / 64, 2);   // 13 x 20 x 2
        gemm_hh_cell_kernel<<<grid, 256>>>(W_hh_f, W_hh_b, slen, t);
    }

    // 3. Logits
    logits_kernel<<<NSPANS / 32, 512>>>(E, out);
}

// round 17
// speedup vs baseline: 1.4098x; 1.1097x over previous
#include <cuda_runtime.h>
#include <math.h>
#include <stdint.h>

// Problem constants
#define BSZ 64
#define SEQ 512
#define DIM 768
#define NSPANS 1280
#define LMAX 5
#define H 200
#define G4 800          // 4*H
#define NENT 16
#define MROWS (NSPANS*LMAX)   // 6400

// Scratch (device globals)
__device__ float d_xg    [2ll * MROWS * G4];
__device__ float d_h     [2ll * 2 * NSPANS * H];   // [parity][dir][n][hh]
__device__ float d_c     [2ll * NSPANS * H];
__device__ float d_sum   [2ll * NSPANS * H];
__device__ int   d_offset[NSPANS + 1];
__device__ int   d_rowmap[MROWS];

#define HBUF (2ll * NSPANS * H)

// ---------------------------------------------------------------------------
// tf32 helpers
// ---------------------------------------------------------------------------
__device__ __forceinline__ uint32_t f2tf32(float f) {
    uint32_t r;
    asm("cvt.rna.tf32.f32 %0, %1;" : "=r"(r) : "f"(f));
    return r;
}

__device__ __forceinline__ void mma_tf32(float* c, const uint32_t* a, const uint32_t* b) {
    asm volatile(
        "mma.sync.aligned.m16n8k8.row.col.f32.tf32.tf32.f32 "
        "{%0,%1,%2,%3}, {%4,%5,%6,%7}, {%8,%9}, {%0,%1,%2,%3};"
        : "+f"(c[0]), "+f"(c[1]), "+f"(c[2]), "+f"(c[3])
        : "r"(a[0]), "r"(a[1]), "r"(a[2]), "r"(a[3]), "r"(b[0]), "r"(b[1]));
}

__device__ __forceinline__ float sigm(float x) { return 1.f / (1.f + expf(-x)); }

#define BK 32
#define PAD 4
#define LDSROW (BK + PAD)   // 36 uints per row (R4/R8 proven layout)

// ---------------------------------------------------------------------------
// Compaction: offsets = exclusive-prefix(slen); rowmap[off+l] = (n<<3)|l
// ---------------------------------------------------------------------------
__global__ void compact_kernel(const int* __restrict__ slen)
{
    __shared__ int part[256];
    int tid = threadIdx.x;
    int base = tid * 5;
    int loc[5], s = 0;
#pragma unroll
    for (int i = 0; i < 5; i++) { loc[i] = s; s += slen[base + i]; }
    part[tid] = s;
    __syncthreads();
    for (int off = 1; off < 256; off <<= 1) {
        int v = (tid >= off) ? part[tid - off] : 0;
        __syncthreads();
        part[tid] += v;
        __syncthreads();
    }
    int pre = (tid == 0) ? 0 : part[tid - 1];
#pragma unroll
    for (int i = 0; i < 5; i++) {
        int n = base + i;
        int off = pre + loc[i];
        d_offset[n] = off;
        int ln = slen[n];
        for (int l = 0; l < ln; l++)
            d_rowmap[off + l] = (n << 3) | l;
    }
    if (tid == 255) d_offset[NSPANS] = part[255];
}

// ---------------------------------------------------------------------------
// xg GEMM, fused gather, compacted rows, REGISTER DOUBLE-BUFFERED mainloop.
// BM=128, BN=64, 8 warps (4Mx2N), warp tile 32x32.
// ---------------------------------------------------------------------------
__global__ __launch_bounds__(256)
void gemm_xg_kernel(const float* __restrict__ hidden,
                    const int* __restrict__ tok,
                    const int* __restrict__ slen,
                    const int* __restrict__ sbatch,
                    const float* __restrict__ Wf, const float* __restrict__ bif,
                    const float* __restrict__ bhf,
                    const float* __restrict__ Wb, const float* __restrict__ bib,
                    const float* __restrict__ bhb)
{
    const int BM = 128, BN = 64, K = DIM, N = G4;
    int m0 = blockIdx.y * BM;
    int count = d_offset[NSPANS];
    if (m0 >= count) return;

    __shared__ uint32_t As[BM][LDSROW];
    __shared__ uint32_t Bs[BN][LDSROW];
    __shared__ const float* rowptr[BM];

    int dir = blockIdx.z;
    const float* W  = dir ? Wb : Wf;
    const float* c1 = dir ? bib : bif;
    const float* c2 = dir ? bhb : bhf;
    float* C        = d_xg + (size_t)dir * MROWS * G4;

    int tid  = threadIdx.x;
    int warp = tid >> 5, lane = tid & 31;
    int wm = warp & 3, wn = warp >> 2;
    int grp = lane >> 2, qid = lane & 3;
    int n0 = blockIdx.x * BN;

    if (tid < BM) {
        int r = m0 + tid;
        const float* p = nullptr;
        if (r < count) {
            int rm = d_rowmap[r];
            int n  = rm >> 3;
            int l  = rm & 7;
            int ln = slen[n];
            int sl = dir ? (ln - 1 - l) : l;
            int t  = tok[n * LMAX + sl];
            int b  = sbatch[n];
            p = hidden + ((size_t)b * SEQ + t) * DIM;
        }
        rowptr[tid] = p;
    }
    __syncthreads();

    float acc[2][4][4];
#pragma unroll
    for (int i = 0; i < 2; i++)
#pragma unroll
        for (int j = 0; j < 4; j++)
#pragma unroll
            for (int q = 0; q < 4; q++) acc[i][j][q] = 0.f;

    const int lrow = tid >> 3;
    const int lcol = (tid & 7) * 4;

    const float* arow[4];
#pragma unroll
    for (int p = 0; p < 4; p++) arow[p] = rowptr[lrow + p * 32];
    bool bval = (n0 + lrow) < N;         // B row guard (pass 0: rows 0..31)
    bool bval2 = (n0 + lrow + 32) < N;   // pass 1: rows 32..63

    // Prefetch tile 0 into registers
    float4 ra[4], rb[2];
#pragma unroll
    for (int p = 0; p < 4; p++)
        ra[p] = arow[p] ? *(const float4*)(arow[p] + lcol)
                        : make_float4(0.f, 0.f, 0.f, 0.f);
    rb[0] = bval  ? *(const float4*)(W + (size_t)(n0 + lrow) * DIM + lcol)
                  : make_float4(0.f, 0.f, 0.f, 0.f);
    rb[1] = bval2 ? *(const float4*)(W + (size_t)(n0 + lrow + 32) * DIM + lcol)
                  : make_float4(0.f, 0.f, 0.f, 0.f);

    for (int kt = 0; kt < K; kt += BK) {
        // Store current registers (cvt to tf32) into smem tiles
#pragma unroll
        for (int p = 0; p < 4; p++) {
            uint4 t;
            t.x = f2tf32(ra[p].x); t.y = f2tf32(ra[p].y);
            t.z = f2tf32(ra[p].z); t.w = f2tf32(ra[p].w);
            *(uint4*)&As[lrow + p * 32][lcol] = t;
        }
        {
            uint4 t;
            t.x = f2tf32(rb[0].x); t.y = f2tf32(rb[0].y);
            t.z = f2tf32(rb[0].z); t.w = f2tf32(rb[0].w);
            *(uint4*)&Bs[lrow][lcol] = t;
            t.x = f2tf32(rb[1].x); t.y = f2tf32(rb[1].y);
            t.z = f2tf32(rb[1].z); t.w = f2tf32(rb[1].w);
            *(uint4*)&Bs[lrow + 32][lcol] = t;
        }
        __syncthreads();

        // Prefetch next tile into registers (overlaps with mma phase below)
        int kn = kt + BK;
        if (kn < K) {
#pragma unroll
            for (int p = 0; p < 4; p++)
                ra[p] = arow[p] ? *(const float4*)(arow[p] + kn + lcol)
                                : make_float4(0.f, 0.f, 0.f, 0.f);
            rb[0] = bval  ? *(const float4*)(W + (size_t)(n0 + lrow) * DIM + kn + lcol)
                          : make_float4(0.f, 0.f, 0.f, 0.f);
            rb[1] = bval2 ? *(const float4*)(W + (size_t)(n0 + lrow + 32) * DIM + kn + lcol)
                          : make_float4(0.f, 0.f, 0.f, 0.f);
        }

        // mma phase
#pragma unroll
        for (int ks = 0; ks < BK / 8; ks++) {
            uint32_t af[2][4], bf[4][2];
#pragma unroll
            for (int i = 0; i < 2; i++) {
                int mr = wm * 32 + i * 16;
                af[i][0] = As[mr + grp    ][ks * 8 + qid    ];
                af[i][1] = As[mr + grp + 8][ks * 8 + qid    ];
                af[i][2] = As[mr + grp    ][ks * 8 + qid + 4];
                af[i][3] = As[mr + grp + 8][ks * 8 + qid + 4];
            }
#pragma unroll
            for (int j = 0; j < 4; j++) {
                int nr = wn * 32 + j * 8;
                bf[j][0] = Bs[nr + grp][ks * 8 + qid    ];
                bf[j][1] = Bs[nr + grp][ks * 8 + qid + 4];
            }
#pragma unroll
            for (int i = 0; i < 2; i++)
#pragma unroll
                for (int j = 0; j < 4; j++)
                    mma_tf32(acc[i][j], af[i], bf[j]);
        }
        __syncthreads();
    }

#pragma unroll
    for (int i = 0; i < 2; i++) {
#pragma unroll
        for (int j = 0; j < 4; j++) {
            int m = m0 + wm * 32 + i * 16 + grp;
            int n = n0 + wn * 32 + j * 8 + qid * 2;
            if (n < N) {
                float bb0 = c1[n] + c2[n];
                float bb1 = c1[n + 1] + c2[n + 1];
                C[(size_t)m * G4 + n]           = acc[i][j][0] + bb0;
                C[(size_t)m * G4 + n + 1]       = acc[i][j][1] + bb1;
                C[(size_t)(m + 8) * G4 + n]     = acc[i][j][2] + bb0;
                C[(size_t)(m + 8) * G4 + n + 1] = acc[i][j][3] + bb1;
            }
        }
    }
}

// ---------------------------------------------------------------------------
// Fused hh GEMM + cell (R8 verbatim). BM=64 spans, BN=64 = 4 gates x 16 hh.
// Column map: local n -> W row (n>>4)*H + hh_base + (n&15).
// h double-buffered: reads parity (t-1)&1, writes t&1.
// grid = (13, 20, 2)
// ---------------------------------------------------------------------------
__global__ __launch_bounds__(256)
void gemm_hh_cell_kernel(const float* __restrict__ Wf, const float* __restrict__ Wb,
                         const int* __restrict__ slen, int t)
{
    const int BM = 64, BN = 64, K = H;
    __shared__ uint32_t As[BM][LDSROW];
    __shared__ uint32_t Bs[BN][LDSROW];
    __shared__ float Gs[BM][BN + 4];
    __shared__ int   xrow[BM];
    __shared__ int   lens[BM];

    int dir = blockIdx.z;
    const float* A     = d_h + ((t - 1) & 1) * HBUF + (size_t)dir * NSPANS * H;
    float*       h_out = d_h + (t & 1) * HBUF;
    const float* W  = dir ? Wb : Wf;
    const float* XG = d_xg + (size_t)dir * MROWS * G4;

    int tid  = threadIdx.x;
    int warp = tid >> 5, lane = tid & 31;
    int wm = warp & 1, wn = warp >> 1;
    int grp = lane >> 2, qid = lane & 3;
    int m0 = blockIdx.y * BM;
    int hh_base = blockIdx.x * 16;

    if (tid < BM) {
        int n  = m0 + tid;
        int ln = slen[n];
        lens[tid] = ln;
        int tt = t < ln ? t : (ln - 1);
        xrow[tid] = d_offset[n] + tt;
    }

    float acc[2][2][4];
#pragma unroll
    for (int i = 0; i < 2; i++)
#pragma unroll
        for (int j = 0; j < 2; j++)
#pragma unroll
            for (int q = 0; q < 4; q++) acc[i][j][q] = 0.f;

    const int lrow = tid >> 3;
    const int lcol = (tid & 7) * 4;

    for (int kt = 0; kt < K; kt += BK) {
#pragma unroll
        for (int p = 0; p < BM / 32; p++) {
            int m = lrow + p * 32;
            int k = kt + lcol;
            float4 v = make_float4(0.f, 0.f, 0.f, 0.f);
            if (k < K)
                v = *(const float4*)(A + (size_t)(m0 + m) * H + k);
            uint4 tt;
            tt.x = f2tf32(v.x); tt.y = f2tf32(v.y);
            tt.z = f2tf32(v.z); tt.w = f2tf32(v.w);
            *(uint4*)&As[m][lcol] = tt;
        }
#pragma unroll
        for (int p = 0; p < BN / 32; p++) {
            int n = lrow + p * 32;
            int hhi = hh_base + (n & 15);
            int grow = (n >> 4) * H + hhi;
            int k = kt + lcol;
            float4 v = make_float4(0.f, 0.f, 0.f, 0.f);
            if (hhi < H && k < K)
                v = *(const float4*)(W + (size_t)grow * H + k);
            uint4 tt;
            tt.x = f2tf32(v.x); tt.y = f2tf32(v.y);
            tt.z = f2tf32(v.z); tt.w = f2tf32(v.w);
            *(uint4*)&Bs[n][lcol] = tt;
        }
        __syncthreads();

#pragma unroll
        for (int ks = 0; ks < BK / 8; ks++) {
            uint32_t af[2][4], bf[2][2];
#pragma unroll
            for (int i = 0; i < 2; i++) {
                int mr = wm * 32 + i * 16;
                af[i][0] = As[mr + grp    ][ks * 8 + qid    ];
                af[i][1] = As[mr + grp + 8][ks * 8 + qid    ];
                af[i][2] = As[mr + grp    ][ks * 8 + qid + 4];
                af[i][3] = As[mr + grp + 8][ks * 8 + qid + 4];
            }
#pragma unroll
            for (int j = 0; j < 2; j++) {
                int nr = wn * 16 + j * 8;
                bf[j][0] = Bs[nr + grp][ks * 8 + qid    ];
                bf[j][1] = Bs[nr + grp][ks * 8 + qid + 4];
            }
#pragma unroll
            for (int i = 0; i < 2; i++)
#pragma unroll
                for (int j = 0; j < 2; j++)
                    mma_tf32(acc[i][j], af[i], bf[j]);
        }
        __syncthreads();
    }

    // Stage gate tile to smem
#pragma unroll
    for (int i = 0; i < 2; i++) {
#pragma unroll
        for (int j = 0; j < 2; j++) {
            int m = wm * 32 + i * 16 + grp;
            int n = wn * 16 + j * 8 + qid * 2;
            Gs[m][n]         = acc[i][j][0];
            Gs[m][n + 1]     = acc[i][j][1];
            Gs[m + 8][n]     = acc[i][j][2];
            Gs[m + 8][n + 1] = acc[i][j][3];
        }
    }
    __syncthreads();

    // Cell phase: 64x16 items, 4 per thread
#pragma unroll
    for (int it = 0; it < 4; it++) {
        int id = tid + it * 256;
        int m  = id >> 4;
        int hl = id & 15;
        int hhi = hh_base + hl;
        if (hhi >= H) continue;

        size_t xb = (size_t)xrow[m] * G4 + hhi;
        float gi = Gs[m][hl     ] + XG[xb];
        float gf = Gs[m][16 + hl] + XG[xb + H];
        float gg = Gs[m][32 + hl] + XG[xb + 2 * H];
        float go = Gs[m][48 + hl] + XG[xb + 3 * H];

        size_t sidx = (size_t)dir * NSPANS * H + (size_t)(m0 + m) * H + hhi;
        float cn = sigm(gf) * d_c[sidx] + sigm(gi) * tanhf(gg);
        float hn = sigm(go) * tanhf(cn);
        d_c[sidx]   = cn;
        h_out[sidx] = hn;
        if (t < lens[m]) d_sum[sidx] += hn;
    }
}

// ---------------------------------------------------------------------------
// t=0 cell: gates = xg[offset[n]] (h=0). Writes h parity 0, c, sum.
// ---------------------------------------------------------------------------
__global__ void lstm_cell0(const int* __restrict__ slen)
{
    int idx = blockIdx.x * blockDim.x + threadIdx.x;
    if (idx >= 2 * NSPANS * H) return;
    int hh  = idx % H;
    int n   = (idx / H) % NSPANS;
    int dir = idx / (H * NSPANS);

    int row = d_offset[n];
    const float* g = d_xg + (size_t)dir * MROWS * G4 + (size_t)row * G4;
    float gi = g[hh];
    float gg = g[2 * H + hh];
    float go = g[3 * H + hh];

    float cn = sigm(gi) * tanhf(gg);
    float hn = sigm(go) * tanhf(cn);
    d_c[idx] = cn;
    d_h[idx] = hn;                  // parity 0
    d_sum[idx] = hn;                // slen >= 1
}

// ---------------------------------------------------------------------------
// Logits (R8 plain version)
// ---------------------------------------------------------------------------
__global__ void logits_kernel(const float* __restrict__ E,
                              float* __restrict__ out)
{
    int idx = blockIdx.x * blockDim.x + threadIdx.x;
    if (idx >= NSPANS * NENT) return;
    int e = idx % NENT;
    int n = idx / NENT;

    const float4* sf = (const float4*)(d_sum + (size_t)n * H);
    const float4* sb = (const float4*)(d_sum + (size_t)NSPANS * H + (size_t)n * H);
    const float4* er = (const float4*)(E + (size_t)e * 2 * H);

    float acc = 0.f;
#pragma unroll
    for (int j = 0; j < H / 4; j++) {
        float4 a = sf[j], b = er[j];
        acc += a.x * b.x + a.y * b.y + a.z * b.z + a.w * b.w;
    }
#pragma unroll
    for (int j = 0; j < H / 4; j++) {
        float4 a = sb[j], b = er[H / 4 + j];
        acc += a.x * b.x + a.y * b.y + a.z * b.z + a.w * b.w;
    }
    out[idx] = acc;
}

// ---------------------------------------------------------------------------
// Launch
// ---------------------------------------------------------------------------
extern "C" void kernel_launch(void* const* d_in, const int* in_sizes, int n_in,
                              void* d_out, int out_size)
{
    const float* hidden = (const float*)d_in[0];
    const int*   tok    = (const int*)d_in[1];
    const int*   slen   = (const int*)d_in[2];
    const int*   sbatch = (const int*)d_in[3];
    const float* W_ih_f = (const float*)d_in[4];
    const float* W_hh_f = (const float*)d_in[5];
    const float* b_ih_f = (const float*)d_in[6];
    const float* b_hh_f = (const float*)d_in[7];
    const float* W_ih_b = (const float*)d_in[8];
    const float* W_hh_b = (const float*)d_in[9];
    const float* b_ih_b = (const float*)d_in[10];
    const float* b_hh_b = (const float*)d_in[11];
    const float* E      = (const float*)d_in[12];
    float* out          = (float*)d_out;

    // 0. Row compaction
    compact_kernel<<<1, 256>>>(slen);

    // 1. xg GEMM, fused gather, compacted rows: grid 13 x 50 x 2 (self-trim)
    {
        dim3 grid((G4 + 63) / 64, MROWS / 128, 2);
        gemm_xg_kernel<<<grid, 256>>>(hidden, tok, slen, sbatch,
                                      W_ih_f, b_ih_f, b_hh_f,
                                      W_ih_b, b_ih_b, b_hh_b);
    }

    // 2. Recurrence
    {
        const int ct = 256;
        lstm_cell0<<<(2 * NSPANS * H + ct - 1) / ct, ct>>>(slen);
    }
    for (int t = 1; t < LMAX; t++) {
        dim3 grid((H + 15) / 16, NSPANS / 64, 2);   // 13 x 20 x 2
        gemm_hh_cell_kernel<<<grid, 256>>>(W_hh_f, W_hh_b, slen, t);
    }

    // 3. Logits
    logits_kernel<<<(NSPANS * NENT + 127) / 128, 128>>>(E, out);
}